// round 15
// baseline (speedup 1.0000x reference)
#include <cuda_runtime.h>
#include <cuda_fp16.h>
#include <math.h>

#define NN 100000
#define EE 3200000
#define HIDD 64
#define BN_EPS 1e-5f
#define NSB 200         // scan blocks (co-resident, grid barrier)
#define SCH 512         // threads per scan block (NSB*SCH = 102400 >= NN)

// ---- scratch (device globals; allocation-free) ----
__device__ int g_is64;
__device__ int g_ctr;                 // grid barrier arrivals
__device__ volatile int g_phase;      // grid barrier sense
__device__ __align__(16) int     g_deg[NN];
__device__ __align__(16) int     g_off[NN + 1];
__device__ __align__(16) int     g_cur[NN];
__device__ __align__(16) float   g_dinv[NN];
__device__ __align__(16) int     g_csr[EE];
__device__ __align__(16) __half2 g_hsh[NN * 32];   // fp16 messages (64 dims = 32 half2)
__device__ __align__(16) __half2 g_acth[NN * 32];  // fp16 activations (layer-1 out)
__device__ __align__(16) float   g_h3[NN];
__device__ __align__(16) int     g_bsum[NSB];

// ---- fused: zero degree counters + dtype detect (last block detects) ----
__global__ void init_detect(const int* __restrict__ ei_w) {
    if (blockIdx.x == gridDim.x - 1) {
        __shared__ int sor;
        if (threadIdx.x == 0) sor = 0;
        __syncthreads();
        int acc = 0;
        for (int i = threadIdx.x; i < 8192; i += blockDim.x)
            acc |= ei_w[2 * i + 1];
        if (acc) atomicOr(&sor, 1);
        __syncthreads();
        if (threadIdx.x == 0) g_is64 = (sor == 0) ? 1 : 0;
    } else {
        int i = blockIdx.x * blockDim.x + threadIdx.x;
        if (i < NN) g_deg[i] = 0;
    }
}

// ---- degree count, reading dst straight from edge_index (4 edges/thread) ----
__global__ void __launch_bounds__(256) count_kernel(const void* __restrict__ ei) {
    int i = blockIdx.x * blockDim.x + threadIdx.x;   // [0, EE/4)
    int d0, d1, d2, d3;
    if (g_is64) {
        const longlong2* p = (const longlong2*)ei + (EE / 2);  // dst block
        longlong2 a = p[2 * i], b = p[2 * i + 1];
        d0 = (int)a.x; d1 = (int)a.y; d2 = (int)b.x; d3 = (int)b.y;
    } else {
        const int4* p = (const int4*)((const int*)ei + EE);
        int4 a = p[i];
        d0 = a.x; d1 = a.y; d2 = a.z; d3 = a.w;
    }
    if ((unsigned)d0 < NN) atomicAdd(&g_deg[d0], 1);
    if ((unsigned)d1 < NN) atomicAdd(&g_deg[d1], 1);
    if ((unsigned)d2 < NN) atomicAdd(&g_deg[d2], 1);
    if ((unsigned)d3 < NN) atomicAdd(&g_deg[d3], 1);
}

// ---- grid barrier over NSB co-resident blocks ----
__device__ __forceinline__ void grid_bar() {
    __syncthreads();
    if (threadIdx.x == 0) {
        int old = g_phase;
        __threadfence();
        if (atomicAdd(&g_ctr, 1) == NSB - 1) {
            g_ctr = 0;
            __threadfence();
            g_phase = old ^ 1;
        } else {
            while (g_phase == old) { }
            __threadfence();
        }
    }
    __syncthreads();
}

// ---- fused scan: block sums | barrier | block prefix + offsets/cur/dinv ----
__global__ void __launch_bounds__(SCH, 2) scan_all() {
    const int t = threadIdx.x;
    const int i = blockIdx.x * SCH + t;
    const int lane = t & 31, w = t >> 5;
    __shared__ int wsum[SCH / 32];
    __shared__ int wpre[SCH / 32];
    __shared__ int s_bpre;

    const int d = (i < NN) ? g_deg[i] : 0;

    // phase 1: per-block degree sum
    {
        int s = d;
#pragma unroll
        for (int o = 16; o > 0; o >>= 1) s += __shfl_xor_sync(0xffffffffu, s, o);
        if (lane == 0) wsum[w] = s;
        __syncthreads();
        if (t == 0) {
            int tot = 0;
#pragma unroll
            for (int k = 0; k < SCH / 32; k++) tot += wsum[k];
            g_bsum[blockIdx.x] = tot;
        }
    }
    grid_bar();

    // phase 2: block prefix (warp 0) + local exclusive scan + outputs
    if (t < 32) {
        int sum = 0;
        for (int j = t; j < blockIdx.x; j += 32) sum += g_bsum[j];
#pragma unroll
        for (int o = 16; o > 0; o >>= 1) sum += __shfl_xor_sync(0xffffffffu, sum, o);
        if (t == 0) s_bpre = sum;
    }
    int x = d;
#pragma unroll
    for (int o = 1; o < 32; o <<= 1) {
        int y = __shfl_up_sync(0xffffffffu, x, o);
        if (lane >= o) x += y;
    }
    if (lane == 31) wsum[w] = x;
    __syncthreads();
    if (t == 0) {
        int run = 0;
#pragma unroll
        for (int k = 0; k < SCH / 32; k++) { wpre[k] = run; run += wsum[k]; }
        if (blockIdx.x == gridDim.x - 1) g_off[NN] = s_bpre + run;
    }
    __syncthreads();
    if (i < NN) {
        int excl = s_bpre + wpre[w] + x - d;
        g_off[i] = excl;
        g_cur[i] = excl;
        g_dinv[i] = rsqrtf((float)d + 1.0f);
    }
}

// ---- CSR fill, reading src/dst straight from edge_index (4 edges/thread) ----
__global__ void __launch_bounds__(256) fill_kernel(const void* __restrict__ ei) {
    int i = blockIdx.x * blockDim.x + threadIdx.x;   // [0, EE/4)
    int s0, s1, s2, s3, d0, d1, d2, d3;
    if (g_is64) {
        const longlong2* ps = (const longlong2*)ei;
        const longlong2* pd = ps + (EE / 2);
        longlong2 a = ps[2 * i], b = ps[2 * i + 1];
        longlong2 c = pd[2 * i], e = pd[2 * i + 1];
        s0 = (int)a.x; s1 = (int)a.y; s2 = (int)b.x; s3 = (int)b.y;
        d0 = (int)c.x; d1 = (int)c.y; d2 = (int)e.x; d3 = (int)e.y;
    } else {
        const int4* ps = (const int4*)ei;
        const int4* pd = (const int4*)((const int*)ei + EE);
        int4 a = ps[i], c = pd[i];
        s0 = a.x; s1 = a.y; s2 = a.z; s3 = a.w;
        d0 = c.x; d1 = c.y; d2 = c.z; d3 = c.w;
    }
    if ((unsigned)d0 < NN && (unsigned)s0 < NN) g_csr[atomicAdd(&g_cur[d0], 1)] = s0;
    if ((unsigned)d1 < NN && (unsigned)s1 < NN) g_csr[atomicAdd(&g_cur[d1], 1)] = s1;
    if ((unsigned)d2 < NN && (unsigned)s2 < NN) g_csr[atomicAdd(&g_cur[d2], 1)] = s2;
    if ((unsigned)d3 < NN && (unsigned)s3 < NN) g_csr[atomicAdd(&g_cur[d3], 1)] = s3;
}

// ---- GEMM: hsh[n,64] = fp16((X[n,:K] @ W[K,64]) * dinv[n])
//      X is fp32 (XHALF=false) or fp16 half2 (XHALF=true) ----
template <int K, bool XHALF>
__global__ void __launch_bounds__(256) gemm_h16(const void* __restrict__ X,
                                                const float* __restrict__ W,
                                                __half2* __restrict__ out) {
    __shared__ float Xs[64][68];
    __shared__ float Ws[64][64];
    const int t = threadIdx.x;
    const int lane = t & 31;
    const int w = t >> 5;
    const int row0 = blockIdx.x * 64;
    const int rbase = w * 8 + ((lane >> 4) << 2);  // 4 rows per thread
    const int c4 = lane & 15;

    unsigned long long acc[4][2];
#pragma unroll
    for (int j = 0; j < 4; j++) { acc[j][0] = 0ull; acc[j][1] = 0ull; }

    const int HALVES = K / 64;
    for (int h = 0; h < HALVES; h++) {
#pragma unroll
        for (int p = 0; p < 4; p++) {
            int idx = t + p * 256;
            int kk = idx >> 4, q = idx & 15;
            reinterpret_cast<float4*>(&Ws[kk][0])[q] =
                reinterpret_cast<const float4*>(W)[(size_t)(h * 64 + kk) * 16 + q];
        }
#pragma unroll
        for (int p = 0; p < 4; p++) {
            int idx = t + p * 256;
            int r = idx >> 4, q = idx & 15;
            int gr = row0 + r; if (gr >= NN) gr = NN - 1;
            if (XHALF) {
                uint2 hv = reinterpret_cast<const uint2*>(X)[(size_t)gr * (K / 4) + h * 16 + q];
                float2 f0 = __half22float2(*reinterpret_cast<__half2*>(&hv.x));
                float2 f1 = __half22float2(*reinterpret_cast<__half2*>(&hv.y));
                reinterpret_cast<float4*>(&Xs[r][0])[q] = make_float4(f0.x, f0.y, f1.x, f1.y);
            } else {
                reinterpret_cast<float4*>(&Xs[r][0])[q] =
                    reinterpret_cast<const float4*>(X)[(size_t)gr * (K / 4) + h * 16 + q];
            }
        }
        __syncthreads();

        unsigned wb = (unsigned)__cvta_generic_to_shared(&Ws[0][c4 * 4]);
#pragma unroll 16
        for (int kk = 0; kk < 64; kk++) {
            unsigned long long w01, w23;
            asm("ld.shared.v2.u64 {%0, %1}, [%2];"
                : "=l"(w01), "=l"(w23) : "r"(wb + kk * 256));
#pragma unroll
            for (int j = 0; j < 4; j++) {
                float xv = Xs[rbase + j][kk];
                unsigned long long xx;
                asm("mov.b64 %0, {%1, %1};" : "=l"(xx) : "f"(xv));
                asm("fma.rn.f32x2 %0, %1, %2, %3;"
                    : "=l"(acc[j][0]) : "l"(xx), "l"(w01), "l"(acc[j][0]));
                asm("fma.rn.f32x2 %0, %1, %2, %3;"
                    : "=l"(acc[j][1]) : "l"(xx), "l"(w23), "l"(acc[j][1]));
            }
        }
        __syncthreads();
    }

#pragma unroll
    for (int j = 0; j < 4; j++) {
        int r = row0 + rbase + j;
        if (r < NN) {
            float d = g_dinv[r];
            float lo, hi;
            asm("mov.b64 {%0, %1}, %2;" : "=f"(lo), "=f"(hi) : "l"(acc[j][0]));
            __half2 h01 = __float22half2_rn(make_float2(lo * d, hi * d));
            asm("mov.b64 {%0, %1}, %2;" : "=f"(lo), "=f"(hi) : "l"(acc[j][1]));
            __half2 h23 = __float22half2_rn(make_float2(lo * d, hi * d));
            uint2 packed;
            packed.x = *reinterpret_cast<unsigned*>(&h01);
            packed.y = *reinterpret_cast<unsigned*>(&h23);
            reinterpret_cast<uint2*>(out)[(size_t)r * 16 + c4] = packed;
        }
    }
}

// ---- gather (fp16 msgs, fp32 accum) + bias + BN + ReLU -> fp16 act ----
__global__ void __launch_bounds__(256) gather_bn_relu(const __half2* __restrict__ hs,
                                                      __half2* __restrict__ out,
                                                      const float* __restrict__ b,
                                                      const float* __restrict__ g,
                                                      const float* __restrict__ beta,
                                                      const float* __restrict__ m,
                                                      const float* __restrict__ v) {
    int warp = threadIdx.x >> 5;
    int lane = threadIdx.x & 31;
    int node = blockIdx.x * 8 + warp;
    if (node >= NN) return;

    float2 acc = __half22float2(hs[(size_t)node * 32 + lane]);  // self-loop term
    int e0 = g_off[node], e1 = g_off[node + 1];
#pragma unroll 4
    for (int e = e0; e < e1; e++) {
        int s = g_csr[e];
        float2 xx = __half22float2(hs[(size_t)s * 32 + lane]);
        acc.x += xx.x; acc.y += xx.y;
    }
    float di = g_dinv[node];
    int k0 = lane * 2;
    float s0 = g[k0] * rsqrtf(v[k0] + BN_EPS);
    float s1 = g[k0 + 1] * rsqrtf(v[k0 + 1] + BN_EPS);
    float z0 = (acc.x * di + b[k0]     - m[k0])     * s0 + beta[k0];
    float z1 = (acc.y * di + b[k0 + 1] - m[k0 + 1]) * s1 + beta[k0 + 1];
    out[(size_t)node * 32 + lane] =
        __float22half2_rn(make_float2(fmaxf(z0, 0.f), fmaxf(z1, 0.f)));
}

// ---- layer-2 gather + BN + ReLU + fused W3 dot -> g_h3 ----
__global__ void __launch_bounds__(256) gather2_dot(const __half2* __restrict__ hs,
                                                   const float* __restrict__ b,
                                                   const float* __restrict__ g,
                                                   const float* __restrict__ beta,
                                                   const float* __restrict__ m,
                                                   const float* __restrict__ v,
                                                   const float* __restrict__ W3) {
    int warp = threadIdx.x >> 5;
    int lane = threadIdx.x & 31;
    int node = blockIdx.x * 8 + warp;
    if (node >= NN) return;

    float2 acc = __half22float2(hs[(size_t)node * 32 + lane]);
    int e0 = g_off[node], e1 = g_off[node + 1];
#pragma unroll 4
    for (int e = e0; e < e1; e++) {
        int s = g_csr[e];
        float2 xx = __half22float2(hs[(size_t)s * 32 + lane]);
        acc.x += xx.x; acc.y += xx.y;
    }
    float di = g_dinv[node];
    int k0 = lane * 2;
    float s0 = g[k0] * rsqrtf(v[k0] + BN_EPS);
    float s1 = g[k0 + 1] * rsqrtf(v[k0 + 1] + BN_EPS);
    float z0 = (acc.x * di + b[k0]     - m[k0])     * s0 + beta[k0];
    float z1 = (acc.y * di + b[k0 + 1] - m[k0 + 1]) * s1 + beta[k0 + 1];
    float o0 = fmaxf(z0, 0.f), o1 = fmaxf(z1, 0.f);

    float2 w3 = reinterpret_cast<const float2*>(W3)[lane];
    float part = o0 * w3.x + o1 * w3.y;
#pragma unroll
    for (int o = 16; o > 0; o >>= 1) part += __shfl_xor_sync(0xffffffffu, part, o);
    if (lane == 0) g_h3[node] = part * di;
}

// ---- layer-3 gather + sigmoid, warp per node ----
__global__ void __launch_bounds__(256) gather3_sigmoid(const float* __restrict__ b3,
                                                       float* __restrict__ out) {
    int warp = threadIdx.x >> 5;
    int lane = threadIdx.x & 31;
    int node = blockIdx.x * 8 + warp;
    if (node >= NN) return;
    int e0 = g_off[node], e1 = g_off[node + 1];
    float a = 0.f;
    for (int e = e0 + lane; e < e1; e += 32) a += g_h3[g_csr[e]];
#pragma unroll
    for (int o = 16; o > 0; o >>= 1) a += __shfl_xor_sync(0xffffffffu, a, o);
    if (lane == 0) {
        float z = (a + g_h3[node]) * g_dinv[node] + b3[0];
        out[node] = 1.0f / (1.0f + expf(-z));
    }
}

extern "C" void kernel_launch(void* const* d_in, const int* in_sizes, int n_in,
                              void* d_out, int out_size) {
    const float* x   = (const float*)d_in[0];
    const void*  ei  = d_in[1];
    const float* W1  = (const float*)d_in[2];
    const float* b1  = (const float*)d_in[3];
    const float* W2  = (const float*)d_in[4];
    const float* b2  = (const float*)d_in[5];
    const float* W3  = (const float*)d_in[6];
    const float* b3  = (const float*)d_in[7];
    const float* g1  = (const float*)d_in[8];
    const float* be1 = (const float*)d_in[9];
    const float* m1  = (const float*)d_in[10];
    const float* v1  = (const float*)d_in[11];
    const float* g2  = (const float*)d_in[12];
    const float* be2 = (const float*)d_in[13];
    const float* m2  = (const float*)d_in[14];
    const float* v2  = (const float*)d_in[15];

    __half2* hsh = nullptr; __half2* acth = nullptr;
    cudaGetSymbolAddress((void**)&hsh, g_hsh);
    cudaGetSymbolAddress((void**)&acth, g_acth);

    static cudaStream_t s_side = nullptr;
    static cudaEvent_t e_dinv = nullptr, e_join = nullptr;
    if (s_side == nullptr) {
        cudaStreamCreateWithFlags(&s_side, cudaStreamNonBlocking);
        cudaEventCreateWithFlags(&e_dinv, cudaEventDisableTiming);
        cudaEventCreateWithFlags(&e_join, cudaEventDisableTiming);
    }

    // main stream: CSR build (degrees -> offsets/dinv)
    init_detect<<<(NN + 255) / 256 + 1, 256>>>((const int*)ei);
    count_kernel<<<EE / 4 / 256, 256>>>(ei);
    scan_all<<<NSB, SCH>>>();
    cudaEventRecord(e_dinv, 0);

    // side stream: gemm1 with dinv fused, hidden under fill
    cudaStreamWaitEvent(s_side, e_dinv, 0);
    gemm_h16<128, false><<<(NN + 63) / 64, 256, 0, s_side>>>(x, W1, hsh);
    cudaEventRecord(e_join, s_side);

    fill_kernel<<<EE / 4 / 256, 256>>>(ei);

    // join, then layer-1 aggregation (writes fp16 act)
    cudaStreamWaitEvent(0, e_join, 0);
    gather_bn_relu<<<NN / 8, 256>>>(hsh, acth, b1, g1, be1, m1, v1);

    // layer 2: gemm reads fp16 act; then gather (+ fused layer-3 projection)
    gemm_h16<64, true><<<(NN + 63) / 64, 256>>>(acth, W2, hsh);
    gather2_dot<<<NN / 8, 256>>>(hsh, b2, g2, be2, m2, v2, W3);

    // layer 3
    gather3_sigmoid<<<NN / 8, 256>>>(b3, (float*)d_out);
}

// round 16
// speedup vs baseline: 1.0015x; 1.0015x over previous
#include <cuda_runtime.h>
#include <cuda_fp16.h>
#include <math.h>

#define NN 100000
#define EE 3200000
#define HIDD 64
#define BN_EPS 1e-5f
#define NSB 200         // scan blocks (co-resident, grid barrier)
#define SCH 512         // threads per scan block (NSB*SCH = 102400 >= NN)

// ---- scratch (device globals; allocation-free) ----
__device__ int g_is64;
__device__ int g_ctr;                 // grid barrier arrivals
__device__ volatile int g_phase;      // grid barrier sense
__device__ __align__(16) int     g_deg[NN];
__device__ __align__(16) int     g_off[NN + 1];
__device__ __align__(16) int     g_cur[NN];
__device__ __align__(16) float   g_dinv[NN];
__device__ __align__(16) int     g_csr[EE];
__device__ __align__(16) __half2 g_hsh[NN * 32];   // fp16 messages (64 dims = 32 half2)
__device__ __align__(16) __half2 g_acth[NN * 32];  // fp16 activations (layer-1 out)
__device__ __align__(16) float   g_h3[NN];
__device__ __align__(16) int     g_bsum[NSB];

// ---- fused: zero degree counters + dtype detect (last block detects) ----
__global__ void init_detect(const int* __restrict__ ei_w) {
    if (blockIdx.x == gridDim.x - 1) {
        __shared__ int sor;
        if (threadIdx.x == 0) sor = 0;
        __syncthreads();
        int acc = 0;
        for (int i = threadIdx.x; i < 8192; i += blockDim.x)
            acc |= ei_w[2 * i + 1];
        if (acc) atomicOr(&sor, 1);
        __syncthreads();
        if (threadIdx.x == 0) g_is64 = (sor == 0) ? 1 : 0;
    } else {
        int i = blockIdx.x * blockDim.x + threadIdx.x;
        if (i < NN) g_deg[i] = 0;
    }
}

// ---- degree count, reading dst straight from edge_index (4 edges/thread) ----
__global__ void __launch_bounds__(256) count_kernel(const void* __restrict__ ei) {
    int i = blockIdx.x * blockDim.x + threadIdx.x;   // [0, EE/4)
    int d0, d1, d2, d3;
    if (g_is64) {
        const longlong2* p = (const longlong2*)ei + (EE / 2);  // dst block
        longlong2 a = p[2 * i], b = p[2 * i + 1];
        d0 = (int)a.x; d1 = (int)a.y; d2 = (int)b.x; d3 = (int)b.y;
    } else {
        const int4* p = (const int4*)((const int*)ei + EE);
        int4 a = p[i];
        d0 = a.x; d1 = a.y; d2 = a.z; d3 = a.w;
    }
    if ((unsigned)d0 < NN) atomicAdd(&g_deg[d0], 1);
    if ((unsigned)d1 < NN) atomicAdd(&g_deg[d1], 1);
    if ((unsigned)d2 < NN) atomicAdd(&g_deg[d2], 1);
    if ((unsigned)d3 < NN) atomicAdd(&g_deg[d3], 1);
}

// ---- grid barrier over NSB co-resident blocks ----
__device__ __forceinline__ void grid_bar() {
    __syncthreads();
    if (threadIdx.x == 0) {
        int old = g_phase;
        __threadfence();
        if (atomicAdd(&g_ctr, 1) == NSB - 1) {
            g_ctr = 0;
            __threadfence();
            g_phase = old ^ 1;
        } else {
            while (g_phase == old) { }
            __threadfence();
        }
    }
    __syncthreads();
}

// ---- fused scan: block sums | barrier | block prefix + offsets/cur/dinv ----
__global__ void __launch_bounds__(SCH, 2) scan_all() {
    const int t = threadIdx.x;
    const int i = blockIdx.x * SCH + t;
    const int lane = t & 31, w = t >> 5;
    __shared__ int wsum[SCH / 32];
    __shared__ int wpre[SCH / 32];
    __shared__ int s_bpre;

    const int d = (i < NN) ? g_deg[i] : 0;

    // phase 1: per-block degree sum
    {
        int s = d;
#pragma unroll
        for (int o = 16; o > 0; o >>= 1) s += __shfl_xor_sync(0xffffffffu, s, o);
        if (lane == 0) wsum[w] = s;
        __syncthreads();
        if (t == 0) {
            int tot = 0;
#pragma unroll
            for (int k = 0; k < SCH / 32; k++) tot += wsum[k];
            g_bsum[blockIdx.x] = tot;
        }
    }
    grid_bar();

    // phase 2: block prefix (warp 0) + local exclusive scan + outputs
    if (t < 32) {
        int sum = 0;
        for (int j = t; j < blockIdx.x; j += 32) sum += g_bsum[j];
#pragma unroll
        for (int o = 16; o > 0; o >>= 1) sum += __shfl_xor_sync(0xffffffffu, sum, o);
        if (t == 0) s_bpre = sum;
    }
    int x = d;
#pragma unroll
    for (int o = 1; o < 32; o <<= 1) {
        int y = __shfl_up_sync(0xffffffffu, x, o);
        if (lane >= o) x += y;
    }
    if (lane == 31) wsum[w] = x;
    __syncthreads();
    if (t == 0) {
        int run = 0;
#pragma unroll
        for (int k = 0; k < SCH / 32; k++) { wpre[k] = run; run += wsum[k]; }
        if (blockIdx.x == gridDim.x - 1) g_off[NN] = s_bpre + run;
    }
    __syncthreads();
    if (i < NN) {
        int excl = s_bpre + wpre[w] + x - d;
        g_off[i] = excl;
        g_cur[i] = excl;
        g_dinv[i] = rsqrtf((float)d + 1.0f);
    }
}

// ---- CSR fill, reading src/dst straight from edge_index (4 edges/thread) ----
__global__ void __launch_bounds__(256) fill_kernel(const void* __restrict__ ei) {
    int i = blockIdx.x * blockDim.x + threadIdx.x;   // [0, EE/4)
    int s0, s1, s2, s3, d0, d1, d2, d3;
    if (g_is64) {
        const longlong2* ps = (const longlong2*)ei;
        const longlong2* pd = ps + (EE / 2);
        longlong2 a = ps[2 * i], b = ps[2 * i + 1];
        longlong2 c = pd[2 * i], e = pd[2 * i + 1];
        s0 = (int)a.x; s1 = (int)a.y; s2 = (int)b.x; s3 = (int)b.y;
        d0 = (int)c.x; d1 = (int)c.y; d2 = (int)e.x; d3 = (int)e.y;
    } else {
        const int4* ps = (const int4*)ei;
        const int4* pd = (const int4*)((const int*)ei + EE);
        int4 a = ps[i], c = pd[i];
        s0 = a.x; s1 = a.y; s2 = a.z; s3 = a.w;
        d0 = c.x; d1 = c.y; d2 = c.z; d3 = c.w;
    }
    if ((unsigned)d0 < NN && (unsigned)s0 < NN) g_csr[atomicAdd(&g_cur[d0], 1)] = s0;
    if ((unsigned)d1 < NN && (unsigned)s1 < NN) g_csr[atomicAdd(&g_cur[d1], 1)] = s1;
    if ((unsigned)d2 < NN && (unsigned)s2 < NN) g_csr[atomicAdd(&g_cur[d2], 1)] = s2;
    if ((unsigned)d3 < NN && (unsigned)s3 < NN) g_csr[atomicAdd(&g_cur[d3], 1)] = s3;
}

// ---- GEMM: hsh[n,64] = fp16((X[n,:K] @ W[K,64]) * dinv[n])
//      X is fp32 (XHALF=false) or fp16 half2 (XHALF=true)
//      launch_bounds(256,4): cap 64 regs -> 4 blocks/SM (occ 50%) ----
template <int K, bool XHALF>
__global__ void __launch_bounds__(256, 4) gemm_h16(const void* __restrict__ X,
                                                   const float* __restrict__ W,
                                                   __half2* __restrict__ out) {
    __shared__ float Xs[64][68];
    __shared__ float Ws[64][64];
    const int t = threadIdx.x;
    const int lane = t & 31;
    const int w = t >> 5;
    const int row0 = blockIdx.x * 64;
    const int rbase = w * 8 + ((lane >> 4) << 2);  // 4 rows per thread
    const int c4 = lane & 15;

    unsigned long long acc[4][2];
#pragma unroll
    for (int j = 0; j < 4; j++) { acc[j][0] = 0ull; acc[j][1] = 0ull; }

    const int HALVES = K / 64;
    for (int h = 0; h < HALVES; h++) {
#pragma unroll
        for (int p = 0; p < 4; p++) {
            int idx = t + p * 256;
            int kk = idx >> 4, q = idx & 15;
            reinterpret_cast<float4*>(&Ws[kk][0])[q] =
                reinterpret_cast<const float4*>(W)[(size_t)(h * 64 + kk) * 16 + q];
        }
#pragma unroll
        for (int p = 0; p < 4; p++) {
            int idx = t + p * 256;
            int r = idx >> 4, q = idx & 15;
            int gr = row0 + r; if (gr >= NN) gr = NN - 1;
            if (XHALF) {
                uint2 hv = reinterpret_cast<const uint2*>(X)[(size_t)gr * (K / 4) + h * 16 + q];
                float2 f0 = __half22float2(*reinterpret_cast<__half2*>(&hv.x));
                float2 f1 = __half22float2(*reinterpret_cast<__half2*>(&hv.y));
                reinterpret_cast<float4*>(&Xs[r][0])[q] = make_float4(f0.x, f0.y, f1.x, f1.y);
            } else {
                reinterpret_cast<float4*>(&Xs[r][0])[q] =
                    reinterpret_cast<const float4*>(X)[(size_t)gr * (K / 4) + h * 16 + q];
            }
        }
        __syncthreads();

        unsigned wb = (unsigned)__cvta_generic_to_shared(&Ws[0][c4 * 4]);
#pragma unroll 8
        for (int kk = 0; kk < 64; kk++) {
            unsigned long long w01, w23;
            asm("ld.shared.v2.u64 {%0, %1}, [%2];"
                : "=l"(w01), "=l"(w23) : "r"(wb + kk * 256));
#pragma unroll
            for (int j = 0; j < 4; j++) {
                float xv = Xs[rbase + j][kk];
                unsigned long long xx;
                asm("mov.b64 %0, {%1, %1};" : "=l"(xx) : "f"(xv));
                asm("fma.rn.f32x2 %0, %1, %2, %3;"
                    : "=l"(acc[j][0]) : "l"(xx), "l"(w01), "l"(acc[j][0]));
                asm("fma.rn.f32x2 %0, %1, %2, %3;"
                    : "=l"(acc[j][1]) : "l"(xx), "l"(w23), "l"(acc[j][1]));
            }
        }
        __syncthreads();
    }

#pragma unroll
    for (int j = 0; j < 4; j++) {
        int r = row0 + rbase + j;
        if (r < NN) {
            float d = g_dinv[r];
            float lo, hi;
            asm("mov.b64 {%0, %1}, %2;" : "=f"(lo), "=f"(hi) : "l"(acc[j][0]));
            __half2 h01 = __float22half2_rn(make_float2(lo * d, hi * d));
            asm("mov.b64 {%0, %1}, %2;" : "=f"(lo), "=f"(hi) : "l"(acc[j][1]));
            __half2 h23 = __float22half2_rn(make_float2(lo * d, hi * d));
            uint2 packed;
            packed.x = *reinterpret_cast<unsigned*>(&h01);
            packed.y = *reinterpret_cast<unsigned*>(&h23);
            reinterpret_cast<uint2*>(out)[(size_t)r * 16 + c4] = packed;
        }
    }
}

// ---- gather (fp16 msgs, fp32 accum) + bias + BN + ReLU -> fp16 act ----
__global__ void __launch_bounds__(256) gather_bn_relu(const __half2* __restrict__ hs,
                                                      __half2* __restrict__ out,
                                                      const float* __restrict__ b,
                                                      const float* __restrict__ g,
                                                      const float* __restrict__ beta,
                                                      const float* __restrict__ m,
                                                      const float* __restrict__ v) {
    int warp = threadIdx.x >> 5;
    int lane = threadIdx.x & 31;
    int node = blockIdx.x * 8 + warp;
    if (node >= NN) return;

    float2 acc = __half22float2(hs[(size_t)node * 32 + lane]);  // self-loop term
    int e0 = g_off[node], e1 = g_off[node + 1];
#pragma unroll 4
    for (int e = e0; e < e1; e++) {
        int s = g_csr[e];
        float2 xx = __half22float2(hs[(size_t)s * 32 + lane]);
        acc.x += xx.x; acc.y += xx.y;
    }
    float di = g_dinv[node];
    int k0 = lane * 2;
    float s0 = g[k0] * rsqrtf(v[k0] + BN_EPS);
    float s1 = g[k0 + 1] * rsqrtf(v[k0 + 1] + BN_EPS);
    float z0 = (acc.x * di + b[k0]     - m[k0])     * s0 + beta[k0];
    float z1 = (acc.y * di + b[k0 + 1] - m[k0 + 1]) * s1 + beta[k0 + 1];
    out[(size_t)node * 32 + lane] =
        __float22half2_rn(make_float2(fmaxf(z0, 0.f), fmaxf(z1, 0.f)));
}

// ---- layer-2 gather + BN + ReLU + fused W3 dot -> g_h3 ----
__global__ void __launch_bounds__(256) gather2_dot(const __half2* __restrict__ hs,
                                                   const float* __restrict__ b,
                                                   const float* __restrict__ g,
                                                   const float* __restrict__ beta,
                                                   const float* __restrict__ m,
                                                   const float* __restrict__ v,
                                                   const float* __restrict__ W3) {
    int warp = threadIdx.x >> 5;
    int lane = threadIdx.x & 31;
    int node = blockIdx.x * 8 + warp;
    if (node >= NN) return;

    float2 acc = __half22float2(hs[(size_t)node * 32 + lane]);
    int e0 = g_off[node], e1 = g_off[node + 1];
#pragma unroll 4
    for (int e = e0; e < e1; e++) {
        int s = g_csr[e];
        float2 xx = __half22float2(hs[(size_t)s * 32 + lane]);
        acc.x += xx.x; acc.y += xx.y;
    }
    float di = g_dinv[node];
    int k0 = lane * 2;
    float s0 = g[k0] * rsqrtf(v[k0] + BN_EPS);
    float s1 = g[k0 + 1] * rsqrtf(v[k0 + 1] + BN_EPS);
    float z0 = (acc.x * di + b[k0]     - m[k0])     * s0 + beta[k0];
    float z1 = (acc.y * di + b[k0 + 1] - m[k0 + 1]) * s1 + beta[k0 + 1];
    float o0 = fmaxf(z0, 0.f), o1 = fmaxf(z1, 0.f);

    float2 w3 = reinterpret_cast<const float2*>(W3)[lane];
    float part = o0 * w3.x + o1 * w3.y;
#pragma unroll
    for (int o = 16; o > 0; o >>= 1) part += __shfl_xor_sync(0xffffffffu, part, o);
    if (lane == 0) g_h3[node] = part * di;
}

// ---- layer-3 gather + sigmoid, warp per node ----
__global__ void __launch_bounds__(256) gather3_sigmoid(const float* __restrict__ b3,
                                                       float* __restrict__ out) {
    int warp = threadIdx.x >> 5;
    int lane = threadIdx.x & 31;
    int node = blockIdx.x * 8 + warp;
    if (node >= NN) return;
    int e0 = g_off[node], e1 = g_off[node + 1];
    float a = 0.f;
    for (int e = e0 + lane; e < e1; e += 32) a += g_h3[g_csr[e]];
#pragma unroll
    for (int o = 16; o > 0; o >>= 1) a += __shfl_xor_sync(0xffffffffu, a, o);
    if (lane == 0) {
        float z = (a + g_h3[node]) * g_dinv[node] + b3[0];
        out[node] = 1.0f / (1.0f + expf(-z));
    }
}

extern "C" void kernel_launch(void* const* d_in, const int* in_sizes, int n_in,
                              void* d_out, int out_size) {
    const float* x   = (const float*)d_in[0];
    const void*  ei  = d_in[1];
    const float* W1  = (const float*)d_in[2];
    const float* b1  = (const float*)d_in[3];
    const float* W2  = (const float*)d_in[4];
    const float* b2  = (const float*)d_in[5];
    const float* W3  = (const float*)d_in[6];
    const float* b3  = (const float*)d_in[7];
    const float* g1  = (const float*)d_in[8];
    const float* be1 = (const float*)d_in[9];
    const float* m1  = (const float*)d_in[10];
    const float* v1  = (const float*)d_in[11];
    const float* g2  = (const float*)d_in[12];
    const float* be2 = (const float*)d_in[13];
    const float* m2  = (const float*)d_in[14];
    const float* v2  = (const float*)d_in[15];

    __half2* hsh = nullptr; __half2* acth = nullptr;
    cudaGetSymbolAddress((void**)&hsh, g_hsh);
    cudaGetSymbolAddress((void**)&acth, g_acth);

    static cudaStream_t s_side = nullptr;
    static cudaEvent_t e_dinv = nullptr, e_join = nullptr;
    if (s_side == nullptr) {
        cudaStreamCreateWithFlags(&s_side, cudaStreamNonBlocking);
        cudaEventCreateWithFlags(&e_dinv, cudaEventDisableTiming);
        cudaEventCreateWithFlags(&e_join, cudaEventDisableTiming);
    }

    // main stream: CSR build (degrees -> offsets/dinv)
    init_detect<<<(NN + 255) / 256 + 1, 256>>>((const int*)ei);
    count_kernel<<<EE / 4 / 256, 256>>>(ei);
    scan_all<<<NSB, SCH>>>();
    cudaEventRecord(e_dinv, 0);

    // side stream: gemm1 with dinv fused, hidden under fill
    cudaStreamWaitEvent(s_side, e_dinv, 0);
    gemm_h16<128, false><<<(NN + 63) / 64, 256, 0, s_side>>>(x, W1, hsh);
    cudaEventRecord(e_join, s_side);

    fill_kernel<<<EE / 4 / 256, 256>>>(ei);

    // join, then layer-1 aggregation (writes fp16 act)
    cudaStreamWaitEvent(0, e_join, 0);
    gather_bn_relu<<<NN / 8, 256>>>(hsh, acth, b1, g1, be1, m1, v1);

    // layer 2: gemm reads fp16 act; then gather (+ fused layer-3 projection)
    gemm_h16<64, true><<<(NN + 63) / 64, 256>>>(acth, W2, hsh);
    gather2_dot<<<NN / 8, 256>>>(hsh, b2, g2, be2, m2, v2, W3);

    // layer 3
    gather3_sigmoid<<<NN / 8, 256>>>(b3, (float*)d_out);
}

// round 17
// speedup vs baseline: 1.0055x; 1.0040x over previous
#include <cuda_runtime.h>
#include <cuda_fp16.h>
#include <math.h>

#define NN 100000
#define EE 3200000
#define HIDD 64
#define BN_EPS 1e-5f
#define NSB 200         // scan blocks (co-resident, grid barrier)
#define SCH 512         // threads per scan block (NSB*SCH = 102400 >= NN)

// ---- scratch (device globals; allocation-free) ----
__device__ int g_is64;
__device__ int g_ctr;                 // grid barrier arrivals
__device__ volatile int g_phase;      // grid barrier sense
__device__ __align__(16) int     g_deg[NN];
__device__ __align__(16) int     g_off[NN + 1];
__device__ __align__(16) int     g_cur[NN];
__device__ __align__(16) float   g_dinv[NN];
__device__ __align__(16) int     g_csr[EE];
__device__ __align__(16) __half2 g_hsh[NN * 32];   // fp16 messages (64 dims = 32 half2)
__device__ __align__(16) __half2 g_acth[NN * 32];  // fp16 activations (layer-1 out)
__device__ __align__(16) float   g_h3[NN];
__device__ __align__(16) int     g_bsum[NSB];

// ---- fused: zero degree counters + dtype detect (last block detects) ----
__global__ void init_detect(const int* __restrict__ ei_w) {
    if (blockIdx.x == gridDim.x - 1) {
        __shared__ int sor;
        if (threadIdx.x == 0) sor = 0;
        __syncthreads();
        int acc = 0;
        for (int i = threadIdx.x; i < 8192; i += blockDim.x)
            acc |= ei_w[2 * i + 1];
        if (acc) atomicOr(&sor, 1);
        __syncthreads();
        if (threadIdx.x == 0) g_is64 = (sor == 0) ? 1 : 0;
    } else {
        int i = blockIdx.x * blockDim.x + threadIdx.x;
        if (i < NN) g_deg[i] = 0;
    }
}

// ---- degree count, reading dst straight from edge_index (4 edges/thread) ----
__global__ void __launch_bounds__(256) count_kernel(const void* __restrict__ ei) {
    int i = blockIdx.x * blockDim.x + threadIdx.x;   // [0, EE/4)
    int d0, d1, d2, d3;
    if (g_is64) {
        const longlong2* p = (const longlong2*)ei + (EE / 2);  // dst block
        longlong2 a = p[2 * i], b = p[2 * i + 1];
        d0 = (int)a.x; d1 = (int)a.y; d2 = (int)b.x; d3 = (int)b.y;
    } else {
        const int4* p = (const int4*)((const int*)ei + EE);
        int4 a = p[i];
        d0 = a.x; d1 = a.y; d2 = a.z; d3 = a.w;
    }
    if ((unsigned)d0 < NN) atomicAdd(&g_deg[d0], 1);
    if ((unsigned)d1 < NN) atomicAdd(&g_deg[d1], 1);
    if ((unsigned)d2 < NN) atomicAdd(&g_deg[d2], 1);
    if ((unsigned)d3 < NN) atomicAdd(&g_deg[d3], 1);
}

// ---- grid barrier over NSB co-resident blocks ----
__device__ __forceinline__ void grid_bar() {
    __syncthreads();
    if (threadIdx.x == 0) {
        int old = g_phase;
        __threadfence();
        if (atomicAdd(&g_ctr, 1) == NSB - 1) {
            g_ctr = 0;
            __threadfence();
            g_phase = old ^ 1;
        } else {
            while (g_phase == old) { }
            __threadfence();
        }
    }
    __syncthreads();
}

// ---- fused scan: block sums | barrier | block prefix + offsets/cur/dinv ----
__global__ void __launch_bounds__(SCH, 2) scan_all() {
    const int t = threadIdx.x;
    const int i = blockIdx.x * SCH + t;
    const int lane = t & 31, w = t >> 5;
    __shared__ int wsum[SCH / 32];
    __shared__ int wpre[SCH / 32];
    __shared__ int s_bpre;

    const int d = (i < NN) ? g_deg[i] : 0;

    // phase 1: per-block degree sum
    {
        int s = d;
#pragma unroll
        for (int o = 16; o > 0; o >>= 1) s += __shfl_xor_sync(0xffffffffu, s, o);
        if (lane == 0) wsum[w] = s;
        __syncthreads();
        if (t == 0) {
            int tot = 0;
#pragma unroll
            for (int k = 0; k < SCH / 32; k++) tot += wsum[k];
            g_bsum[blockIdx.x] = tot;
        }
    }
    grid_bar();

    // phase 2: block prefix (warp 0) + local exclusive scan + outputs
    if (t < 32) {
        int sum = 0;
        for (int j = t; j < blockIdx.x; j += 32) sum += g_bsum[j];
#pragma unroll
        for (int o = 16; o > 0; o >>= 1) sum += __shfl_xor_sync(0xffffffffu, sum, o);
        if (t == 0) s_bpre = sum;
    }
    int x = d;
#pragma unroll
    for (int o = 1; o < 32; o <<= 1) {
        int y = __shfl_up_sync(0xffffffffu, x, o);
        if (lane >= o) x += y;
    }
    if (lane == 31) wsum[w] = x;
    __syncthreads();
    if (t == 0) {
        int run = 0;
#pragma unroll
        for (int k = 0; k < SCH / 32; k++) { wpre[k] = run; run += wsum[k]; }
        if (blockIdx.x == gridDim.x - 1) g_off[NN] = s_bpre + run;
    }
    __syncthreads();
    if (i < NN) {
        int excl = s_bpre + wpre[w] + x - d;
        g_off[i] = excl;
        g_cur[i] = excl;
        g_dinv[i] = rsqrtf((float)d + 1.0f);
    }
}

// ---- CSR fill, reading src/dst straight from edge_index (4 edges/thread) ----
__global__ void __launch_bounds__(256) fill_kernel(const void* __restrict__ ei) {
    int i = blockIdx.x * blockDim.x + threadIdx.x;   // [0, EE/4)
    int s0, s1, s2, s3, d0, d1, d2, d3;
    if (g_is64) {
        const longlong2* ps = (const longlong2*)ei;
        const longlong2* pd = ps + (EE / 2);
        longlong2 a = ps[2 * i], b = ps[2 * i + 1];
        longlong2 c = pd[2 * i], e = pd[2 * i + 1];
        s0 = (int)a.x; s1 = (int)a.y; s2 = (int)b.x; s3 = (int)b.y;
        d0 = (int)c.x; d1 = (int)c.y; d2 = (int)e.x; d3 = (int)e.y;
    } else {
        const int4* ps = (const int4*)ei;
        const int4* pd = (const int4*)((const int*)ei + EE);
        int4 a = ps[i], c = pd[i];
        s0 = a.x; s1 = a.y; s2 = a.z; s3 = a.w;
        d0 = c.x; d1 = c.y; d2 = c.z; d3 = c.w;
    }
    if ((unsigned)d0 < NN && (unsigned)s0 < NN) g_csr[atomicAdd(&g_cur[d0], 1)] = s0;
    if ((unsigned)d1 < NN && (unsigned)s1 < NN) g_csr[atomicAdd(&g_cur[d1], 1)] = s1;
    if ((unsigned)d2 < NN && (unsigned)s2 < NN) g_csr[atomicAdd(&g_cur[d2], 1)] = s2;
    if ((unsigned)d3 < NN && (unsigned)s3 < NN) g_csr[atomicAdd(&g_cur[d3], 1)] = s3;
}

// ---- GEMM: hsh[n,64] = fp16((X[n,:K] @ W[K,64]) * dinv[n])
//      X is fp32 (XHALF=false) or fp16 half2 (XHALF=true)
//      inner loop: 2 k-steps/iter, float2 x-broadcasts (fewer LDS wavefronts) ----
template <int K, bool XHALF>
__global__ void __launch_bounds__(256, 4) gemm_h16(const void* __restrict__ X,
                                                   const float* __restrict__ W,
                                                   __half2* __restrict__ out) {
    __shared__ float Xs[64][68];
    __shared__ float Ws[64][64];
    const int t = threadIdx.x;
    const int lane = t & 31;
    const int w = t >> 5;
    const int row0 = blockIdx.x * 64;
    const int rbase = w * 8 + ((lane >> 4) << 2);  // 4 rows per thread
    const int c4 = lane & 15;

    unsigned long long acc[4][2];
#pragma unroll
    for (int j = 0; j < 4; j++) { acc[j][0] = 0ull; acc[j][1] = 0ull; }

    const int HALVES = K / 64;
    for (int h = 0; h < HALVES; h++) {
#pragma unroll
        for (int p = 0; p < 4; p++) {
            int idx = t + p * 256;
            int kk = idx >> 4, q = idx & 15;
            reinterpret_cast<float4*>(&Ws[kk][0])[q] =
                reinterpret_cast<const float4*>(W)[(size_t)(h * 64 + kk) * 16 + q];
        }
#pragma unroll
        for (int p = 0; p < 4; p++) {
            int idx = t + p * 256;
            int r = idx >> 4, q = idx & 15;
            int gr = row0 + r; if (gr >= NN) gr = NN - 1;
            if (XHALF) {
                uint2 hv = reinterpret_cast<const uint2*>(X)[(size_t)gr * (K / 4) + h * 16 + q];
                float2 f0 = __half22float2(*reinterpret_cast<__half2*>(&hv.x));
                float2 f1 = __half22float2(*reinterpret_cast<__half2*>(&hv.y));
                reinterpret_cast<float4*>(&Xs[r][0])[q] = make_float4(f0.x, f0.y, f1.x, f1.y);
            } else {
                reinterpret_cast<float4*>(&Xs[r][0])[q] =
                    reinterpret_cast<const float4*>(X)[(size_t)gr * (K / 4) + h * 16 + q];
            }
        }
        __syncthreads();

        unsigned wb = (unsigned)__cvta_generic_to_shared(&Ws[0][c4 * 4]);
#pragma unroll 4
        for (int kk = 0; kk < 64; kk += 2) {
            unsigned long long wa01, wa23, wb01, wb23;
            asm("ld.shared.v2.u64 {%0, %1}, [%2];"
                : "=l"(wa01), "=l"(wa23) : "r"(wb + kk * 256));
            asm("ld.shared.v2.u64 {%0, %1}, [%2];"
                : "=l"(wb01), "=l"(wb23) : "r"(wb + kk * 256 + 256));
#pragma unroll
            for (int j = 0; j < 4; j++) {
                float2 xv = *reinterpret_cast<const float2*>(&Xs[rbase + j][kk]);
                unsigned long long xxa, xxb;
                asm("mov.b64 %0, {%1, %1};" : "=l"(xxa) : "f"(xv.x));
                asm("mov.b64 %0, {%1, %1};" : "=l"(xxb) : "f"(xv.y));
                asm("fma.rn.f32x2 %0, %1, %2, %3;"
                    : "=l"(acc[j][0]) : "l"(xxa), "l"(wa01), "l"(acc[j][0]));
                asm("fma.rn.f32x2 %0, %1, %2, %3;"
                    : "=l"(acc[j][1]) : "l"(xxa), "l"(wa23), "l"(acc[j][1]));
                asm("fma.rn.f32x2 %0, %1, %2, %3;"
                    : "=l"(acc[j][0]) : "l"(xxb), "l"(wb01), "l"(acc[j][0]));
                asm("fma.rn.f32x2 %0, %1, %2, %3;"
                    : "=l"(acc[j][1]) : "l"(xxb), "l"(wb23), "l"(acc[j][1]));
            }
        }
        __syncthreads();
    }

#pragma unroll
    for (int j = 0; j < 4; j++) {
        int r = row0 + rbase + j;
        if (r < NN) {
            float d = g_dinv[r];
            float lo, hi;
            asm("mov.b64 {%0, %1}, %2;" : "=f"(lo), "=f"(hi) : "l"(acc[j][0]));
            __half2 h01 = __float22half2_rn(make_float2(lo * d, hi * d));
            asm("mov.b64 {%0, %1}, %2;" : "=f"(lo), "=f"(hi) : "l"(acc[j][1]));
            __half2 h23 = __float22half2_rn(make_float2(lo * d, hi * d));
            uint2 packed;
            packed.x = *reinterpret_cast<unsigned*>(&h01);
            packed.y = *reinterpret_cast<unsigned*>(&h23);
            reinterpret_cast<uint2*>(out)[(size_t)r * 16 + c4] = packed;
        }
    }
}

// ---- gather (fp16 msgs, fp32 accum) + bias + BN + ReLU -> fp16 act ----
__global__ void __launch_bounds__(256) gather_bn_relu(const __half2* __restrict__ hs,
                                                      __half2* __restrict__ out,
                                                      const float* __restrict__ b,
                                                      const float* __restrict__ g,
                                                      const float* __restrict__ beta,
                                                      const float* __restrict__ m,
                                                      const float* __restrict__ v) {
    int warp = threadIdx.x >> 5;
    int lane = threadIdx.x & 31;
    int node = blockIdx.x * 8 + warp;
    if (node >= NN) return;

    float2 acc = __half22float2(hs[(size_t)node * 32 + lane]);  // self-loop term
    int e0 = g_off[node], e1 = g_off[node + 1];
#pragma unroll 4
    for (int e = e0; e < e1; e++) {
        int s = g_csr[e];
        float2 xx = __half22float2(hs[(size_t)s * 32 + lane]);
        acc.x += xx.x; acc.y += xx.y;
    }
    float di = g_dinv[node];
    int k0 = lane * 2;
    float s0 = g[k0] * rsqrtf(v[k0] + BN_EPS);
    float s1 = g[k0 + 1] * rsqrtf(v[k0 + 1] + BN_EPS);
    float z0 = (acc.x * di + b[k0]     - m[k0])     * s0 + beta[k0];
    float z1 = (acc.y * di + b[k0 + 1] - m[k0 + 1]) * s1 + beta[k0 + 1];
    out[(size_t)node * 32 + lane] =
        __float22half2_rn(make_float2(fmaxf(z0, 0.f), fmaxf(z1, 0.f)));
}

// ---- layer-2 gather + BN + ReLU + fused W3 dot -> g_h3 ----
__global__ void __launch_bounds__(256) gather2_dot(const __half2* __restrict__ hs,
                                                   const float* __restrict__ b,
                                                   const float* __restrict__ g,
                                                   const float* __restrict__ beta,
                                                   const float* __restrict__ m,
                                                   const float* __restrict__ v,
                                                   const float* __restrict__ W3) {
    int warp = threadIdx.x >> 5;
    int lane = threadIdx.x & 31;
    int node = blockIdx.x * 8 + warp;
    if (node >= NN) return;

    float2 acc = __half22float2(hs[(size_t)node * 32 + lane]);
    int e0 = g_off[node], e1 = g_off[node + 1];
#pragma unroll 4
    for (int e = e0; e < e1; e++) {
        int s = g_csr[e];
        float2 xx = __half22float2(hs[(size_t)s * 32 + lane]);
        acc.x += xx.x; acc.y += xx.y;
    }
    float di = g_dinv[node];
    int k0 = lane * 2;
    float s0 = g[k0] * rsqrtf(v[k0] + BN_EPS);
    float s1 = g[k0 + 1] * rsqrtf(v[k0 + 1] + BN_EPS);
    float z0 = (acc.x * di + b[k0]     - m[k0])     * s0 + beta[k0];
    float z1 = (acc.y * di + b[k0 + 1] - m[k0 + 1]) * s1 + beta[k0 + 1];
    float o0 = fmaxf(z0, 0.f), o1 = fmaxf(z1, 0.f);

    float2 w3 = reinterpret_cast<const float2*>(W3)[lane];
    float part = o0 * w3.x + o1 * w3.y;
#pragma unroll
    for (int o = 16; o > 0; o >>= 1) part += __shfl_xor_sync(0xffffffffu, part, o);
    if (lane == 0) g_h3[node] = part * di;
}

// ---- layer-3 gather + sigmoid, warp per node ----
__global__ void __launch_bounds__(256) gather3_sigmoid(const float* __restrict__ b3,
                                                       float* __restrict__ out) {
    int warp = threadIdx.x >> 5;
    int lane = threadIdx.x & 31;
    int node = blockIdx.x * 8 + warp;
    if (node >= NN) return;
    int e0 = g_off[node], e1 = g_off[node + 1];
    float a = 0.f;
    for (int e = e0 + lane; e < e1; e += 32) a += g_h3[g_csr[e]];
#pragma unroll
    for (int o = 16; o > 0; o >>= 1) a += __shfl_xor_sync(0xffffffffu, a, o);
    if (lane == 0) {
        float z = (a + g_h3[node]) * g_dinv[node] + b3[0];
        out[node] = 1.0f / (1.0f + expf(-z));
    }
}

extern "C" void kernel_launch(void* const* d_in, const int* in_sizes, int n_in,
                              void* d_out, int out_size) {
    const float* x   = (const float*)d_in[0];
    const void*  ei  = d_in[1];
    const float* W1  = (const float*)d_in[2];
    const float* b1  = (const float*)d_in[3];
    const float* W2  = (const float*)d_in[4];
    const float* b2  = (const float*)d_in[5];
    const float* W3  = (const float*)d_in[6];
    const float* b3  = (const float*)d_in[7];
    const float* g1  = (const float*)d_in[8];
    const float* be1 = (const float*)d_in[9];
    const float* m1  = (const float*)d_in[10];
    const float* v1  = (const float*)d_in[11];
    const float* g2  = (const float*)d_in[12];
    const float* be2 = (const float*)d_in[13];
    const float* m2  = (const float*)d_in[14];
    const float* v2  = (const float*)d_in[15];

    __half2* hsh = nullptr; __half2* acth = nullptr;
    cudaGetSymbolAddress((void**)&hsh, g_hsh);
    cudaGetSymbolAddress((void**)&acth, g_acth);

    static cudaStream_t s_side = nullptr;
    static cudaEvent_t e_dinv = nullptr, e_join = nullptr;
    if (s_side == nullptr) {
        cudaStreamCreateWithFlags(&s_side, cudaStreamNonBlocking);
        cudaEventCreateWithFlags(&e_dinv, cudaEventDisableTiming);
        cudaEventCreateWithFlags(&e_join, cudaEventDisableTiming);
    }

    // main stream: CSR build (degrees -> offsets/dinv)
    init_detect<<<(NN + 255) / 256 + 1, 256>>>((const int*)ei);
    count_kernel<<<EE / 4 / 256, 256>>>(ei);
    scan_all<<<NSB, SCH>>>();
    cudaEventRecord(e_dinv, 0);

    // side stream: gemm1 with dinv fused, hidden under fill
    cudaStreamWaitEvent(s_side, e_dinv, 0);
    gemm_h16<128, false><<<(NN + 63) / 64, 256, 0, s_side>>>(x, W1, hsh);
    cudaEventRecord(e_join, s_side);

    fill_kernel<<<EE / 4 / 256, 256>>>(ei);

    // join, then layer-1 aggregation (writes fp16 act)
    cudaStreamWaitEvent(0, e_join, 0);
    gather_bn_relu<<<NN / 8, 256>>>(hsh, acth, b1, g1, be1, m1, v1);

    // layer 2: gemm reads fp16 act; then gather (+ fused layer-3 projection)
    gemm_h16<64, true><<<(NN + 63) / 64, 256>>>(acth, W2, hsh);
    gather2_dot<<<NN / 8, 256>>>(hsh, b2, g2, be2, m2, v2, W3);

    // layer 3
    gather3_sigmoid<<<NN / 8, 256>>>(b3, (float*)d_out);
}